// round 16
// baseline (speedup 1.0000x reference)
#include <cuda_runtime.h>
#include <cstdint>

#define NN     100000
#define EE     1000000
#define DIN    128
#define DOUT   64
#define DEDGE  11
#define ET     (EE + NN)
#define FULL   0xFFFFFFFFu

// ---------------- scratch (device globals) ----------------------------------
__device__ float  g_xl[NN * DOUT];         // x @ W_l   (25.6 MB)
__device__ float  g_xr[NN * DOUT];         // x @ W_r   (25.6 MB)
__device__ int    g_cnt[NN];               // in-degree
__device__ int    g_off[NN];               // CSR offsets (exclusive scan)
__device__ int    g_cur[NN];               // fill cursors
__device__ float4 g_pack4[EE * 3];         // CSR-ordered rows: 11 attrs + src bits

// ---------------- 0: zero counters ------------------------------------------
__global__ void k_zero() {
    int i = blockIdx.x * blockDim.x + threadIdx.x;
    if (i < NN) g_cnt[i] = 0;
}

// ---------------- 1: in-degree histogram -------------------------------------
__global__ void k_count(const int* __restrict__ ei) {
    int e = blockIdx.x * blockDim.x + threadIdx.x;
    if (e >= EE) return;
    atomicAdd(&g_cnt[__ldg(&ei[EE + e])], 1);
}

// ---------------- 2: exclusive prefix scan (single block) --------------------
__global__ void k_scan() {
    __shared__ int warp_sums[32];
    __shared__ int s_carry, s_total;
    int tid = threadIdx.x;
    int lane = tid & 31, wid = tid >> 5;
    if (tid == 0) s_carry = 0;
    __syncthreads();
    for (int base = 0; base < NN; base += 1024) {
        int i = base + tid;
        int v = (i < NN) ? g_cnt[i] : 0;
        int incl = v;
#pragma unroll
        for (int o = 1; o < 32; o <<= 1) {
            int t = __shfl_up_sync(FULL, incl, o);
            if (lane >= o) incl += t;
        }
        if (lane == 31) warp_sums[wid] = incl;
        __syncthreads();
        if (wid == 0) {
            int ws = warp_sums[lane];
            int wincl = ws;
#pragma unroll
            for (int o = 1; o < 32; o <<= 1) {
                int t = __shfl_up_sync(FULL, wincl, o);
                if (lane >= o) wincl += t;
            }
            warp_sums[lane] = wincl - ws;       // exclusive warp offset
            if (lane == 31) s_total = wincl;    // chunk total
        }
        __syncthreads();
        int excl = incl - v + warp_sums[wid] + s_carry;
        if (i < NN) { g_off[i] = excl; g_cur[i] = excl; }
        __syncthreads();
        if (tid == 0) s_carry += s_total;
        __syncthreads();
    }
}

// ---------------- 3: CSR fill: pack attrs + src into 48B rows ----------------
__global__ void k_fill(const int* __restrict__ ei, const float* __restrict__ ea) {
    int e = blockIdx.x * blockDim.x + threadIdx.x;
    if (e >= EE) return;
    int src = __ldg(&ei[e]);
    int dst = __ldg(&ei[EE + e]);
    int pos = atomicAdd(&g_cur[dst], 1);
    float v[12];
#pragma unroll
    for (int k = 0; k < DEDGE; k++) v[k] = __ldg(&ea[(size_t)e * DEDGE + k]);
    v[11] = __int_as_float(src);
    float4* p = &g_pack4[(size_t)pos * 3];
    p[0] = make_float4(v[0], v[1], v[2],  v[3]);
    p[1] = make_float4(v[4], v[5], v[6],  v[7]);
    p[2] = make_float4(v[8], v[9], v[10], v[11]);
}

// ---------------- 4: tensor-core GEMM (3xTF32), W pre-split in smem ----------
#define SXS   132
#define SWS   72
#define SM_X    0
#define SM_WH  (SM_X + 64 * SXS)            // 8448
#define SM_WLO (SM_WH + 128 * SWS)          // 17664
#define SM_TOT_F (SM_WLO + 128 * SWS)       // 26880 floats = 107520 B
#define TILE_M 64

__device__ __forceinline__ unsigned f2tf(float f) {
    unsigned u;
    asm("cvt.rna.tf32.f32 %0, %1;" : "=r"(u) : "f"(f));
    return u;
}
__device__ __forceinline__ void mma_tf32(float* d, unsigned a0, unsigned a1,
                                         unsigned a2, unsigned a3,
                                         unsigned b0, unsigned b1) {
    asm volatile(
        "mma.sync.aligned.m16n8k8.row.col.f32.tf32.tf32.f32 "
        "{%0,%1,%2,%3}, {%4,%5,%6,%7}, {%8,%9}, {%0,%1,%2,%3};"
        : "+f"(d[0]), "+f"(d[1]), "+f"(d[2]), "+f"(d[3])
        : "r"(a0), "r"(a1), "r"(a2), "r"(a3), "r"(b0), "r"(b1));
}

__global__ void __launch_bounds__(256, 2)
k_gemm(const float* __restrict__ x, const float* __restrict__ W, int is_l) {
    extern __shared__ float sm[];
    float* sx = sm + SM_X;
    float* gout = is_l ? g_xl : g_xr;   // device-side symbol reference (valid)

    int tid  = threadIdx.x;
    int warp = tid >> 5;
    int lane = tid & 31;
    int grp  = lane >> 2;
    int ctid = lane & 3;

    // --- fill W as tf32 hi/lo (once per block, float4-wide) ---
    for (int i = tid; i < (DIN * DOUT) / 4; i += 256) {
        int k = i >> 4, n4 = (i & 15) * 4;
        float4 v = __ldg((const float4*)W + i);
        float4 hi, lo;
        hi.x = __uint_as_float(f2tf(v.x)); lo.x = __uint_as_float(f2tf(v.x - hi.x));
        hi.y = __uint_as_float(f2tf(v.y)); lo.y = __uint_as_float(f2tf(v.y - hi.y));
        hi.z = __uint_as_float(f2tf(v.z)); lo.z = __uint_as_float(f2tf(v.z - hi.z));
        hi.w = __uint_as_float(f2tf(v.w)); lo.w = __uint_as_float(f2tf(v.w - hi.w));
        *(float4*)&sm[SM_WH  + k * SWS + n4] = hi;
        *(float4*)&sm[SM_WLO + k * SWS + n4] = lo;
    }

    // --- load x tile 64 x 128 (zero-pad OOB rows) ---
    int row0 = blockIdx.x * TILE_M;
    {
        const float4* xg = (const float4*)x;
        for (int i = tid; i < TILE_M * 32; i += 256) {
            int r = i >> 5, c4 = i & 31;
            float4 v = make_float4(0.f, 0.f, 0.f, 0.f);
            if (row0 + r < NN) v = xg[(size_t)(row0 + r) * 32 + c4];
            *(float4*)&sx[r * SXS + c4 * 4] = v;
        }
    }
    __syncthreads();

    int rb = (warp & 3) * 16;      // row slab within tile
    int nh = (warp >> 2) * 32;     // n-half base column

    float d[4][4];
#pragma unroll
    for (int t = 0; t < 4; t++)
#pragma unroll
        for (int q = 0; q < 4; q++) d[t][q] = 0.f;

#pragma unroll 1
    for (int k0 = 0; k0 < DIN; k0 += 8) {
        // B fragments: pure LDS, already tf32
        unsigned bh[4][2], bl[4][2];
        const float* ph0 = sm + SM_WH  + (k0 + ctid) * SWS + nh + grp;
        const float* ph1 = sm + SM_WH  + (k0 + ctid + 4) * SWS + nh + grp;
        const float* pl0 = sm + SM_WLO + (k0 + ctid) * SWS + nh + grp;
        const float* pl1 = sm + SM_WLO + (k0 + ctid + 4) * SWS + nh + grp;
#pragma unroll
        for (int t = 0; t < 4; t++) {
            bh[t][0] = __float_as_uint(ph0[8 * t]);
            bh[t][1] = __float_as_uint(ph1[8 * t]);
            bl[t][0] = __float_as_uint(pl0[8 * t]);
            bl[t][1] = __float_as_uint(pl1[8 * t]);
        }
        // A fragment: cvt on the fly (only 4 values)
        float f0 = sx[(rb + grp)     * SXS + k0 + ctid];
        float f1 = sx[(rb + grp + 8) * SXS + k0 + ctid];
        float f2 = sx[(rb + grp)     * SXS + k0 + ctid + 4];
        float f3 = sx[(rb + grp + 8) * SXS + k0 + ctid + 4];
        unsigned a0 = f2tf(f0), a1 = f2tf(f1), a2 = f2tf(f2), a3 = f2tf(f3);
        unsigned l0 = f2tf(f0 - __uint_as_float(a0));
        unsigned l1 = f2tf(f1 - __uint_as_float(a1));
        unsigned l2 = f2tf(f2 - __uint_as_float(a2));
        unsigned l3 = f2tf(f3 - __uint_as_float(a3));
#pragma unroll
        for (int t = 0; t < 4; t++) {
            mma_tf32(d[t], a0, a1, a2, a3, bh[t][0], bh[t][1]);
            mma_tf32(d[t], l0, l1, l2, l3, bh[t][0], bh[t][1]);
            mma_tf32(d[t], a0, a1, a2, a3, bl[t][0], bl[t][1]);
        }
    }

    {
        int r0 = row0 + rb + grp;
        int r1 = r0 + 8;
#pragma unroll
        for (int t = 0; t < 4; t++) {
            int col = nh + 8 * t + 2 * ctid;
            if (r0 < NN)
                *(float2*)&gout[(size_t)r0 * DOUT + col] =
                    make_float2(d[t][0], d[t][1]);
            if (r1 < NN)
                *(float2*)&gout[(size_t)r1 * DOUT + col] =
                    make_float2(d[t][2], d[t][3]);
        }
    }
}

// ---------------- 5: CSR aggregation (R12 compute + packed feed + prefetch) --
// One warp per destination, pair-per-iteration (R12 shape: LDS sWe in loop,
// two plain 5-shfl butterflies). Feed: one coalesced 96B pack load per pair
// (lanes 0-11 edge j, lanes 16-27 edge j+1; slot 11 = src bits), prefetched
// one iteration ahead so its latency hides under the previous pair's compute.
__global__ void __launch_bounds__(256)
k_aggr(const float* __restrict__ We, const float* __restrict__ att,
       float* __restrict__ out) {
    __shared__ float sWe[DEDGE * DOUT];
    __shared__ float sAtt[DOUT];
    for (int i = threadIdx.x; i < DEDGE * DOUT; i += 256) sWe[i] = We[i];
    if (threadIdx.x < DOUT) sAtt[threadIdx.x] = att[threadIdx.x];
    __syncthreads();

    int dst  = (int)((blockIdx.x * blockDim.x + threadIdx.x) >> 5);
    int lane = threadIdx.x & 31;
    int h    = lane >> 4;          // half
    int c    = lane & 15;          // slot within half
    if (dst >= NN) return;

    const float2* sWe2  = (const float2*)sWe;
    const float2* sAtt2 = (const float2*)sAtt;
    float2 at = sAtt2[lane];

    float2 xrv = ((const float2*)g_xr)[(size_t)dst * 32 + lane];

    int start = g_off[dst];
    int deg   = g_cnt[dst];

    float2 acc = make_float2(0.f, 0.f);
    float den = 0.f;
    float attr_s = 0.f;            // per-half partials; folded after loop
    const float* packf = (const float*)g_pack4;

    if (deg > 0) {
        // pack row loader for pair starting at edge j (clamped, predicated)
        int clamp_max = deg - 1;
        float pv;
        {
            int jj = min(h, clamp_max);
            pv = (c < 12) ? __ldg(&packf[(size_t)(start + jj) * 12 + c]) : 0.f;
        }
        for (int j = 0; j < deg; j += 2) {
            // prefetch next pair's pack row (clamped; discarded at loop end)
            float pvn;
            {
                int jj = min(j + 2 + h, clamp_max);
                pvn = (c < 12) ? __ldg(&packf[(size_t)(start + jj) * 12 + c]) : 0.f;
            }

            int src0 = __float_as_int(__shfl_sync(FULL, pv, 11));
            int src1 = __float_as_int(__shfl_sync(FULL, pv, 27));
            float2 xlv0 = ((const float2*)g_xl)[(size_t)src0 * 32 + lane];
            float2 xlv1 = ((const float2*)g_xl)[(size_t)src1 * 32 + lane];
            bool v1ok = (j + 1) < deg;

            if (c < DEDGE && (h == 0 || v1ok)) attr_s += pv;

            float e00 = 0.f, e01 = 0.f, e10 = 0.f, e11 = 0.f;
#pragma unroll
            for (int k = 0; k < DEDGE; k++) {
                float ak0 = __shfl_sync(FULL, pv, k);
                float ak1 = __shfl_sync(FULL, pv, k + 16);
                float2 w = sWe2[k * 32 + lane];
                e00 = fmaf(ak0, w.x, e00);
                e01 = fmaf(ak0, w.y, e01);
                e10 = fmaf(ak1, w.x, e10);
                e11 = fmaf(ak1, w.y, e11);
            }

            float m00 = xlv0.x + xrv.x + e00;  m00 = (m00 >= 0.f) ? m00 : 0.2f * m00;
            float m01 = xlv0.y + xrv.y + e01;  m01 = (m01 >= 0.f) ? m01 : 0.2f * m01;
            float m10 = xlv1.x + xrv.x + e10;  m10 = (m10 >= 0.f) ? m10 : 0.2f * m10;
            float m11 = xlv1.y + xrv.y + e11;  m11 = (m11 >= 0.f) ? m11 : 0.2f * m11;
            float v0 = m00 * at.x + m01 * at.y;
            float v1 = m10 * at.x + m11 * at.y;
#pragma unroll
            for (int o = 16; o > 0; o >>= 1) {
                v0 += __shfl_xor_sync(FULL, v0, o);
                v1 += __shfl_xor_sync(FULL, v1, o);
            }

            float ex0 = __expf(v0);
            float ex1 = v1ok ? __expf(v1) : 0.f;
            den += ex0 + ex1;
            acc.x = fmaf(ex0, xlv0.x, fmaf(ex1, xlv1.x, acc.x));
            acc.y = fmaf(ex0, xlv0.y, fmaf(ex1, xlv1.y, acc.y));

            pv = pvn;
        }
        attr_s += __shfl_xor_sync(FULL, attr_s, 16);  // lanes 0-10 get totals
    }

    // --- self-loop: attr = mean of incoming attrs ---
    {
        float inv = 1.0f / fmaxf((float)deg, 1.0f);
        float av = attr_s * inv;   // valid on lanes 0..10

        float e0 = 0.f, e1 = 0.f;
#pragma unroll
        for (int k = 0; k < DEDGE; k++) {
            float ak = __shfl_sync(FULL, av, k);
            float2 w = sWe2[k * 32 + lane];
            e0 = fmaf(ak, w.x, e0);
            e1 = fmaf(ak, w.y, e1);
        }

        float2 xlv = ((const float2*)g_xl)[(size_t)dst * 32 + lane];
        float m0 = xlv.x + xrv.x + e0;  m0 = (m0 >= 0.f) ? m0 : 0.2f * m0;
        float m1 = xlv.y + xrv.y + e1;  m1 = (m1 >= 0.f) ? m1 : 0.2f * m1;
        float v = m0 * at.x + m1 * at.y;
#pragma unroll
        for (int o = 16; o > 0; o >>= 1)
            v += __shfl_xor_sync(FULL, v, o);

        float ex = __expf(v);
        den += ex;
        acc.x = fmaf(ex, xlv.x, acc.x);
        acc.y = fmaf(ex, xlv.y, acc.y);
    }

    float inv_den = 1.0f / den;
    ((float2*)out)[(size_t)dst * 32 + lane] =
        make_float2(acc.x * inv_den, acc.y * inv_den);
}

// ---------------- launch -----------------------------------------------------
extern "C" void kernel_launch(void* const* d_in, const int* in_sizes, int n_in,
                              void* d_out, int out_size) {
    const float* x   = (const float*)d_in[0];
    const int*   ei  = (const int*)  d_in[1];
    const float* ea  = (const float*)d_in[2];
    const float* Wl  = (const float*)d_in[3];
    const float* Wr  = (const float*)d_in[4];
    const float* We  = (const float*)d_in[5];
    const float* att = (const float*)d_in[6];
    float* out = (float*)d_out;

    cudaFuncSetAttribute(k_gemm, cudaFuncAttributeMaxDynamicSharedMemorySize,
                         SM_TOT_F * 4);

    k_zero <<<(NN + 255) / 256, 256>>>();
    k_count<<<(EE + 255) / 256, 256>>>(ei);
    k_scan <<<1, 1024>>>();
    k_fill <<<(EE + 255) / 256, 256>>>(ei, ea);
    int nblk = (NN + TILE_M - 1) / TILE_M;
    k_gemm <<<nblk, 256, SM_TOT_F * 4>>>(x, Wl, 1);
    k_gemm <<<nblk, 256, SM_TOT_F * 4>>>(x, Wr, 0);
    k_aggr <<<(NN * 32 + 255) / 256, 256>>>(We, att, out);
}